// round 14
// baseline (speedup 1.0000x reference)
#include <cuda_runtime.h>
#include <cuda_fp16.h>

#define B_    4
#define N_    2048
#define F_IN  256
#define H_    8
#define F_OUT 64
#define HF    (H_ * F_OUT)       // 512
#define DEG_CAP 256

// Scratch (device globals: allocation-free per harness rules)
__device__ __half g_h16[(size_t)B_ * N_ * HF];     // [b][n][h][o], fp16
__device__ float  g_atts2[B_ * N_ * H_];           // [b][n][h]
__device__ float  g_attn2[B_ * N_ * H_];           // [b][n][h]

__device__ __forceinline__ unsigned f2tf32(float f) {
    unsigned r;
    asm("cvt.rna.tf32.f32 %0, %1;" : "=r"(r) : "f"(f));
    return r;
}

// -------------------------------------------------------------------------
// Kernel 1: h = X @ W per head via tf32 mma.sync (m16n8k8), fp32 accum.
// CTA = 128 rows x 64 cols (one head). 8 warps in 4x2, each 32x32.
// Epilogue: stage fp32 h tile in smem (union overlay) -> logits + fp16 store.
// -------------------------------------------------------------------------
__global__ __launch_bounds__(256) void gemm_h_tc(const float* __restrict__ X,
                                                 const float* __restrict__ W,
                                                 const float* __restrict__ a_self,
                                                 const float* __restrict__ a_neigh) {
    const int head = blockIdx.y;
    const int b    = blockIdx.x >> 4;          // 16 n-tiles of 128 per batch
    const int n0   = (blockIdx.x & 15) * 128;

    __shared__ union {
        struct {
            unsigned Xs[128][36];   // tf32 bits, 128 rows x 32 k (pad 36)
            unsigned Wsm[32][72];   // tf32 bits, 32 k x 64 o (pad 72)
        } mm;
        float hs[128][66];          // fp32 h tile for epilogue
    } sm;

    const int t    = threadIdx.x;
    const int lane = t & 31;
    const int warp = t >> 5;
    const int wm   = warp >> 1;        // 0..3 -> rows wm*32..+31
    const int wn   = warp & 1;         // 0..1 -> cols wn*32..+31
    const int g    = lane >> 2;        // groupID 0..7
    const int tg   = lane & 3;         // threadID_in_group 0..3

    const float* Xb = X + ((size_t)b * N_ + n0) * F_IN;
    const float* Wh = W + (size_t)head * F_IN * F_OUT;

    float c[2][4][4] = {};             // [mtile][ntile][frag]

    for (int k0 = 0; k0 < F_IN; k0 += 32) {
        {   // X chunk 128x32 -> tf32 smem; each thread 16 consecutive floats
            int row = t >> 1;
            int q   = (t & 1) * 16;
            const float* src = Xb + (size_t)row * F_IN + k0 + q;
            #pragma unroll
            for (int i = 0; i < 4; i++) {
                float4 u = *(const float4*)(src + i * 4);
                sm.mm.Xs[row][q + i * 4 + 0] = f2tf32(u.x);
                sm.mm.Xs[row][q + i * 4 + 1] = f2tf32(u.y);
                sm.mm.Xs[row][q + i * 4 + 2] = f2tf32(u.z);
                sm.mm.Xs[row][q + i * 4 + 3] = f2tf32(u.w);
            }
        }
        {   // W chunk 32x64 -> tf32 smem
            int r = t >> 3;
            int q = (t & 7) * 8;
            const float* src = Wh + (size_t)(k0 + r) * F_OUT + q;
            float4 u0 = *(const float4*)src;
            float4 u1 = *(const float4*)(src + 4);
            sm.mm.Wsm[r][q + 0] = f2tf32(u0.x); sm.mm.Wsm[r][q + 1] = f2tf32(u0.y);
            sm.mm.Wsm[r][q + 2] = f2tf32(u0.z); sm.mm.Wsm[r][q + 3] = f2tf32(u0.w);
            sm.mm.Wsm[r][q + 4] = f2tf32(u1.x); sm.mm.Wsm[r][q + 5] = f2tf32(u1.y);
            sm.mm.Wsm[r][q + 6] = f2tf32(u1.z); sm.mm.Wsm[r][q + 7] = f2tf32(u1.w);
        }
        __syncthreads();

        #pragma unroll
        for (int ks = 0; ks < 4; ks++) {
            unsigned a[2][4];
            #pragma unroll
            for (int mt = 0; mt < 2; mt++) {
                int rbase = wm * 32 + mt * 16;
                a[mt][0] = sm.mm.Xs[rbase + g][ks * 8 + tg];
                a[mt][1] = sm.mm.Xs[rbase + g + 8][ks * 8 + tg];
                a[mt][2] = sm.mm.Xs[rbase + g][ks * 8 + tg + 4];
                a[mt][3] = sm.mm.Xs[rbase + g + 8][ks * 8 + tg + 4];
            }
            #pragma unroll
            for (int nt = 0; nt < 4; nt++) {
                unsigned b0 = sm.mm.Wsm[ks * 8 + tg][wn * 32 + nt * 8 + g];
                unsigned b1 = sm.mm.Wsm[ks * 8 + tg + 4][wn * 32 + nt * 8 + g];
                #pragma unroll
                for (int mt = 0; mt < 2; mt++) {
                    asm volatile(
                        "mma.sync.aligned.m16n8k8.row.col.f32.tf32.tf32.f32 "
                        "{%0,%1,%2,%3}, {%4,%5,%6,%7}, {%8,%9}, {%0,%1,%2,%3};"
                        : "+f"(c[mt][nt][0]), "+f"(c[mt][nt][1]),
                          "+f"(c[mt][nt][2]), "+f"(c[mt][nt][3])
                        : "r"(a[mt][0]), "r"(a[mt][1]), "r"(a[mt][2]), "r"(a[mt][3]),
                          "r"(b0), "r"(b1));
                }
            }
        }
        __syncthreads();
    }

    // store C fragments to fp32 smem tile (overlay — all mma reads done)
    #pragma unroll
    for (int mt = 0; mt < 2; mt++) {
        int row = wm * 32 + mt * 16 + g;
        #pragma unroll
        for (int nt = 0; nt < 4; nt++) {
            int col = wn * 32 + nt * 8 + tg * 2;
            sm.hs[row][col]         = c[mt][nt][0];
            sm.hs[row][col + 1]     = c[mt][nt][1];
            sm.hs[row + 8][col]     = c[mt][nt][2];
            sm.hs[row + 8][col + 1] = c[mt][nt][3];
        }
    }
    __syncthreads();

    // epilogue: thread t: row t>>1, 32-col segment (t&1)*32
    {
        int row = t >> 1;
        int seg = (t & 1) * 32;
        const float* as = a_self  + head * F_OUT + seg;
        const float* an = a_neigh + head * F_OUT + seg;
        float v[32];
        float s = 0.f, nn = 0.f;
        #pragma unroll
        for (int cc = 0; cc < 32; cc++) {
            v[cc] = sm.hs[row][seg + cc];
            s  = fmaf(v[cc], as[cc], s);
            nn = fmaf(v[cc], an[cc], nn);
        }
        s  += __shfl_xor_sync(0xFFFFFFFFu, s, 1);
        nn += __shfl_xor_sync(0xFFFFFFFFu, nn, 1);
        if ((t & 1) == 0) {
            size_t idx = ((size_t)b * N_ + n0 + row) * H_ + head;
            g_atts2[idx] = s;
            g_attn2[idx] = nn;
        }

        __half* dst = g_h16 + ((size_t)b * N_ + n0 + row) * HF + head * F_OUT + seg;
        #pragma unroll
        for (int q = 0; q < 4; q++) {
            __half2 h0 = __floats2half2_rn(v[q * 8 + 0], v[q * 8 + 1]);
            __half2 h1 = __floats2half2_rn(v[q * 8 + 2], v[q * 8 + 3]);
            __half2 h2 = __floats2half2_rn(v[q * 8 + 4], v[q * 8 + 5]);
            __half2 h3 = __floats2half2_rn(v[q * 8 + 6], v[q * 8 + 7]);
            uint4 pk;
            pk.x = *(unsigned*)&h0; pk.y = *(unsigned*)&h1;
            pk.z = *(unsigned*)&h2; pk.w = *(unsigned*)&h3;
            *(uint4*)(dst + q * 8) = pk;
        }
    }
}

// -------------------------------------------------------------------------
// Kernel 2: fused A-row compaction + sparse gather-aggregate (R7/R13 best).
// -------------------------------------------------------------------------
__global__ __launch_bounds__(256) void agg_kernel(const float* __restrict__ A,
                                                  float* __restrict__ out) {
    const int bi = blockIdx.x;          // b*N + i
    const int b  = bi >> 11;
    const int t  = threadIdx.x;
    const int h  = t >> 5;              // warp id == head in gather phases
    const int l  = t & 31;

    __shared__ int   idx_s[DEG_CAP];
    __shared__ float w_s[DEG_CAP][8];
    __shared__ float atts_s[8];
    __shared__ int   wcnt[8];

    // ---- phase 0: compact adjacency row into idx_s ----
    {
        const float* Arow = A + (size_t)bi * N_;
        const int base_col = h * 256 + l * 8;
        float4 va = *(const float4*)(Arow + base_col);
        float4 vb = *(const float4*)(Arow + base_col + 4);
        unsigned m8 = (va.x != 0.0f ? 1u   : 0u) | (va.y != 0.0f ? 2u   : 0u) |
                      (va.z != 0.0f ? 4u   : 0u) | (va.w != 0.0f ? 8u   : 0u) |
                      (vb.x != 0.0f ? 16u  : 0u) | (vb.y != 0.0f ? 32u  : 0u) |
                      (vb.z != 0.0f ? 64u  : 0u) | (vb.w != 0.0f ? 128u : 0u);
        int cnt  = __popc(m8);
        int incl = cnt;
        #pragma unroll
        for (int off = 1; off < 32; off <<= 1) {
            int o = __shfl_up_sync(0xFFFFFFFFu, incl, off);
            if (l >= off) incl += o;
        }
        if (l == 31) wcnt[h] = incl;           // warp total
        int excl = incl - cnt;
        __syncthreads();

        int woff = 0;
        #pragma unroll
        for (int ww = 0; ww < 8; ww++) if (ww < h) woff += wcnt[ww];

        int pos = woff + excl;
        unsigned mm = m8;
        while (mm) {
            int bit = __ffs(mm) - 1;
            mm &= mm - 1u;
            if (pos < DEG_CAP) idx_s[pos] = base_col + bit;
            pos++;
        }
    }
    if (t < 8) atts_s[t] = g_atts2[(size_t)bi * 8 + t];
    __syncthreads();

    int deg = wcnt[0] + wcnt[1] + wcnt[2] + wcnt[3] +
              wcnt[4] + wcnt[5] + wcnt[6] + wcnt[7];
    deg = deg < DEG_CAP ? deg : DEG_CAP;
    const int deg4 = (deg + 3) & ~3;

    // ---- phase 1: weights for all (neighbor, head); pad [deg, deg4) ----
    if (t < deg) {
        int j = idx_s[t];
        const float* an = g_attn2 + ((size_t)(b * N_) + j) * 8;
        float4 a0 = *(const float4*)an;
        float4 a1 = *(const float4*)(an + 4);
        float vals[8] = {a0.x, a0.y, a0.z, a0.w, a1.x, a1.y, a1.z, a1.w};
        float w[8];
        #pragma unroll
        for (int hh = 0; hh < 8; hh++) {
            float x  = atts_s[hh] + vals[hh];
            float sc = fmaxf(x, 0.2f * x);
            w[hh] = __expf(sc);
        }
        *(float4*)&w_s[t][0] = make_float4(w[0], w[1], w[2], w[3]);
        *(float4*)&w_s[t][4] = make_float4(w[4], w[5], w[6], w[7]);
    } else if (t < deg4) {
        idx_s[t] = 0;
        *(float4*)&w_s[t][0] = make_float4(0.f, 0.f, 0.f, 0.f);
        *(float4*)&w_s[t][4] = make_float4(0.f, 0.f, 0.f, 0.f);
    }
    __syncthreads();

    // ---- phase 2: gather + weighted sum. grp = l>>3 picks 1 of 4 nbrs ----
    const int grp = l >> 3;
    const int q8  = (l & 7) * 8;     // 8 halves per lane
    const __half* hb = g_h16 + ((size_t)b * N_) * HF + h * F_OUT + q8;

    float acc[8] = {};
    float dacc = 0.f;

    for (int k = 0; k < deg4; k += 4) {
        int   j = idx_s[k + grp];
        float w = w_s[k + grp][h];
        uint4 v = *(const uint4*)(hb + (unsigned)j * HF);
        float2 f01 = __half22float2(*(__half2*)&v.x);
        float2 f23 = __half22float2(*(__half2*)&v.y);
        float2 f45 = __half22float2(*(__half2*)&v.z);
        float2 f67 = __half22float2(*(__half2*)&v.w);
        acc[0] = fmaf(w, f01.x, acc[0]); acc[1] = fmaf(w, f01.y, acc[1]);
        acc[2] = fmaf(w, f23.x, acc[2]); acc[3] = fmaf(w, f23.y, acc[3]);
        acc[4] = fmaf(w, f45.x, acc[4]); acc[5] = fmaf(w, f45.y, acc[5]);
        acc[6] = fmaf(w, f67.x, acc[6]); acc[7] = fmaf(w, f67.y, acc[7]);
        dacc += w;
    }

    // combine the 4 neighbor-groups (and the denominator) across lanes
    #pragma unroll
    for (int c = 0; c < 8; c++) {
        acc[c] += __shfl_xor_sync(0xFFFFFFFFu, acc[c], 8);
        acc[c] += __shfl_xor_sync(0xFFFFFFFFu, acc[c], 16);
    }
    dacc += __shfl_xor_sync(0xFFFFFFFFu, dacc, 8);
    dacc += __shfl_xor_sync(0xFFFFFFFFu, dacc, 16);

    if (l < 8) {
        float inv = 1.0f / dacc;
        float4 o0, o1;
        o0.x = fmaxf(acc[0] * inv, 0.f); o0.y = fmaxf(acc[1] * inv, 0.f);
        o0.z = fmaxf(acc[2] * inv, 0.f); o0.w = fmaxf(acc[3] * inv, 0.f);
        o1.x = fmaxf(acc[4] * inv, 0.f); o1.y = fmaxf(acc[5] * inv, 0.f);
        o1.z = fmaxf(acc[6] * inv, 0.f); o1.w = fmaxf(acc[7] * inv, 0.f);
        float* op = out + (size_t)bi * HF + h * F_OUT + q8;
        *(float4*)op       = o0;
        *(float4*)(op + 4) = o1;
    }
}

// -------------------------------------------------------------------------
extern "C" void kernel_launch(void* const* d_in, const int* in_sizes, int n_in,
                              void* d_out, int out_size) {
    const float* X       = (const float*)d_in[0];
    const float* A       = (const float*)d_in[1];
    const float* W       = (const float*)d_in[2];
    const float* a_self  = (const float*)d_in[3];
    const float* a_neigh = (const float*)d_in[4];
    float* out = (float*)d_out;

    // 1) h = X @ W per head (tf32 tensor cores, 128x64 CTA) + logits + fp16 store
    gemm_h_tc<<<dim3(16 * B_, H_), 256>>>(X, W, a_self, a_neigh);

    // 2) fused adjacency compaction + sparse softmax aggregation + relu + concat
    agg_kernel<<<B_ * N_, 256>>>(A, out);
}